// round 17
// baseline (speedup 1.0000x reference)
#include <cuda_runtime.h>
#include <cuda_bf16.h>
#include <math.h>

#define BZ 32
#define SZ 128
#define HZ 768
#define MH_ 6
#define KK 4
#define RANK_ROWS 43   // rows per phase rank: ranks 0,1 -> 43; rank 2 -> 42

__constant__ float c_inv[8] = {1.f, 1.f/2.f, 1.f/3.f, 1.f/4.f, 1.f/5.f, 1.f/6.f, 1.f/7.f, 1.f/8.f};

#define CE(x, y) { unsigned long long _a = (x), _b = (y); (x) = _a > _b ? _a : _b; (y) = _a > _b ? _b : _a; }

#define WARP_MERGE4(k0, k1, k2, k3)                                            \
    _Pragma("unroll")                                                          \
    for (int off = 16; off; off >>= 1) {                                       \
        unsigned long long o0 = __shfl_xor_sync(0xFFFFFFFFu, k0, off);         \
        unsigned long long o1 = __shfl_xor_sync(0xFFFFFFFFu, k1, off);         \
        unsigned long long o2 = __shfl_xor_sync(0xFFFFFFFFu, k2, off);         \
        unsigned long long o3 = __shfl_xor_sync(0xFFFFFFFFu, k3, off);         \
        unsigned long long c0 = k0 > o3 ? k0 : o3;                             \
        unsigned long long c1 = k1 > o2 ? k1 : o2;                             \
        unsigned long long c2 = k2 > o1 ? k2 : o1;                             \
        unsigned long long c3 = k3 > o0 ? k3 : o0;                             \
        CE(c0, c2); CE(c1, c3); CE(c0, c1); CE(c2, c3);                        \
        k0 = c0; k1 = c1; k2 = c2; k3 = c3;                                    \
    }

#define CLUSTER_SYNC() do {                                                    \
    asm volatile("barrier.cluster.arrive.aligned;" ::: "memory");              \
    asm volatile("barrier.cluster.wait.aligned;" ::: "memory");                \
} while (0)

__device__ __forceinline__ unsigned smem_u32(const void* p) {
    return (unsigned)__cvta_generic_to_shared(p);
}

// out layout (floats): implicit[0,512) explicit[512,2560) hs[2560,35328) ts[35328,68096)

__global__ __launch_bounds__(256, 1) __cluster_dims__(4, 1, 1)
void k_all(
    const float* __restrict__ emb,
    const int* __restrict__ mask,
    const float* __restrict__ wh,
    const float* __restrict__ bh_,
    const float* __restrict__ wt,
    const float* __restrict__ bt_,
    const float* __restrict__ wi,
    const float* __restrict__ bi,
    const float* __restrict__ we,
    const float* __restrict__ be,
    float* __restrict__ out)
{
    // identical static layout in every CTA (mapa-compatible)
    __shared__ __align__(8) unsigned long long s_mbar;
    __shared__ float sdot[2][136];                 // tail: row dots (+pad)
    __shared__ unsigned long long cand[2][32];
    __shared__ float topv[2][KK];
    __shared__ int   topi[2][KK];
    __shared__ float partial[8][8];
    __shared__ float sbias[8];                     // 0-3: bi, 4-7: be
    __shared__ float s_bh, s_bt;
    __shared__ int s_len;

    const int bidx = blockIdx.x;
    const int b = bidx >> 2;
    unsigned rank;
    asm("mov.u32 %0, %%cluster_ctarank;" : "=r"(rank));
    const int tid = threadIdx.x;
    const int warp = tid >> 5, lane = tid & 31;
    const float* eb = emb + b * (SZ * HZ);

    // ---- init (tail inits mbar; all CTAs then cluster-sync once) ----
    if (rank == 3) {
        if (tid == 0)
            asm volatile("mbarrier.init.shared.b64 [%0], 3;"
                         :: "r"(smem_u32(&s_mbar)) : "memory");
        if (tid < 4)            sbias[tid] = bi[tid];
        else if (tid < 8)       sbias[tid] = be[tid - 4];
        if (tid == 8)  s_bh = bh_[0];
        if (tid == 9)  s_bt = bt_[0];
        if (tid >= 16 && tid < 32) {      // zero sdot pads [128..136)
            int t2 = tid - 16;
            sdot[t2 >> 3][128 + (t2 & 7)] = 0.f;
        }
        if (warp == 7) {
            int4 mv = ((const int4*)(mask + b * SZ))[lane];
            int v = mv.x + mv.y + mv.z + mv.w;
#pragma unroll
            for (int off = 16; off; off >>= 1) v += __shfl_xor_sync(0xFFFFFFFFu, v, off);
            if (lane == 0) s_len = v;
        }
    }
    CLUSTER_SYNC();

    if (rank < 3) {
        // ============== PHASE CTA: rows [rank*43, ...) dots -> tail DSMEM ==
        const int base = rank * RANK_ROWS;
        const int nrows = (rank == 2) ? 42 : 43;

        float4 wh4[6], wt4[6];
#pragma unroll
        for (int i = 0; i < 6; i++) {
            wh4[i] = ((const float4*)wh)[lane + 32 * i];
            wt4[i] = ((const float4*)wt)[lane + 32 * i];
        }

        // 6 rows per warp, all loads batched (one latency exposure)
        float4 v[6][6];
        bool ok[6];
#pragma unroll
        for (int rr = 0; rr < 6; rr++) {
            int lr = warp * 6 + rr;
            ok[rr] = (lr < nrows);
            if (ok[rr]) {
                const float4* rp = (const float4*)(eb + (base + lr) * HZ);
#pragma unroll
                for (int i = 0; i < 6; i++) v[rr][i] = rp[lane + 32 * i];
            }
        }
        float ah[6], at[6];
#pragma unroll
        for (int rr = 0; rr < 6; rr++) {
            float a = 0.f, t = 0.f;
            if (ok[rr]) {
#pragma unroll
                for (int i = 0; i < 6; i++) {
                    a += v[rr][i].x * wh4[i].x + v[rr][i].y * wh4[i].y
                       + v[rr][i].z * wh4[i].z + v[rr][i].w * wh4[i].w;
                    t += v[rr][i].x * wt4[i].x + v[rr][i].y * wt4[i].y
                       + v[rr][i].z * wt4[i].z + v[rr][i].w * wt4[i].w;
                }
            }
            ah[rr] = a; at[rr] = t;
        }
#pragma unroll
        for (int off = 16; off; off >>= 1) {
#pragma unroll
            for (int rr = 0; rr < 6; rr++) {
                ah[rr] += __shfl_xor_sync(0xFFFFFFFFu, ah[rr], off);
                at[rr] += __shfl_xor_sync(0xFFFFFFFFu, at[rr], off);
            }
        }
        if (lane == 0) {
            // remote base address of sdot in tail CTA (rank 3)
            unsigned rbase;
            asm("mapa.shared::cluster.u32 %0, %1, %2;"
                : "=r"(rbase) : "r"(smem_u32(&sdot[0][0])), "r"(3));
#pragma unroll
            for (int rr = 0; rr < 6; rr++) {
                if (ok[rr]) {
                    int row = base + warp * 6 + rr;
                    asm volatile("st.shared::cluster.f32 [%0], %1;"
                                 :: "r"(rbase + row * 4), "f"(at[rr]) : "memory");
                    asm volatile("st.shared::cluster.f32 [%0], %1;"
                                 :: "r"(rbase + (136 + row) * 4), "f"(ah[rr]) : "memory");
                }
            }
        }
        __syncthreads();
        if (tid == 0) {
            asm volatile("fence.acq_rel.cluster;" ::: "memory");
            unsigned rmbar;
            asm("mapa.shared::cluster.u32 %0, %1, %2;"
                : "=r"(rmbar) : "r"(smem_u32(&s_mbar)), "r"(3));
            asm volatile("mbarrier.arrive.shared::cluster.b64 _, [%0];"
                         :: "r"(rmbar) : "memory");
        }
    } else {
        // ================= TAIL CTA =======================================
        // wait for 3 phase arrivals (parity 0; smem fresh every launch)
        {
            unsigned mb = smem_u32(&s_mbar);
            unsigned done;
            asm volatile(
                "{\n\t.reg .pred p;\n\t"
                "mbarrier.try_wait.parity.acquire.cta.shared::cta.b64 p, [%1], 0;\n\t"
                "selp.b32 %0, 1, 0, p;\n\t}"
                : "=r"(done) : "r"(mb) : "memory");
            if (!done) {
                asm volatile(
                    "{\n\t.reg .pred P1;\n\t"
                    "WL_%=:\n\t"
                    "mbarrier.try_wait.parity.acquire.cta.shared::cta.b64 P1, [%0], 0, 0x989680;\n\t"
                    "@P1 bra.uni WD_%=;\n\t"
                    "bra.uni WL_%=;\n\t"
                    "WD_%=:\n\t}"
                    :: "r"(mb) : "memory");
            }
            asm volatile("fence.acq_rel.cluster;" ::: "memory");
        }

        const int len = s_len;

        // scores: warp = width m; 4 starts per lane; both types per warp
        {
            const int m = warp;
            const float invw = c_inv[m];
            unsigned long long kt[4], kh[4];
#pragma unroll
            for (int ii = 0; ii < 4; ii++) {
                int s = lane + 32 * ii;
                float st = 0.f, sh = 0.f;
                for (int r = 0; r <= m; r++) {
                    st += sdot[0][s + r];
                    sh += sdot[1][s + r];
                }
                bool tv = (s + m) < len;
                bool hv = tv && (m < MH_);
                float vt = tv ? 1.f / (1.f + __expf(-(st * invw + s_bt))) : -1.f;
                float vh = hv ? 1.f / (1.f + __expf(-(sh * invw + s_bh))) : -1.f;
                int gidx = m * SZ + s;
                out[35328 + b * 1024 + gidx] = vt;
                out[2560  + b * 1024 + gidx] = vh;
                unsigned ut = __float_as_uint(vt), uh = __float_as_uint(vh);
                ut = (ut & 0x80000000u) ? ~ut : (ut | 0x80000000u);
                uh = (uh & 0x80000000u) ? ~uh : (uh | 0x80000000u);
                kt[ii] = ((unsigned long long)ut << 32) | (unsigned)(0xFFFFFFFFu - gidx);
                kh[ii] = ((unsigned long long)uh << 32) | (unsigned)(0xFFFFFFFFu - gidx);
            }
            // sort4 desc, both types interleaved
            CE(kt[0], kt[1]); CE(kh[0], kh[1]);
            CE(kt[2], kt[3]); CE(kh[2], kh[3]);
            CE(kt[0], kt[2]); CE(kh[0], kh[2]);
            CE(kt[1], kt[3]); CE(kh[1], kh[3]);
            CE(kt[1], kt[2]); CE(kh[1], kh[2]);
            // interleaved butterfly merges
#pragma unroll
            for (int off = 16; off; off >>= 1) {
                unsigned long long ot0 = __shfl_xor_sync(0xFFFFFFFFu, kt[0], off);
                unsigned long long oh0 = __shfl_xor_sync(0xFFFFFFFFu, kh[0], off);
                unsigned long long ot1 = __shfl_xor_sync(0xFFFFFFFFu, kt[1], off);
                unsigned long long oh1 = __shfl_xor_sync(0xFFFFFFFFu, kh[1], off);
                unsigned long long ot2 = __shfl_xor_sync(0xFFFFFFFFu, kt[2], off);
                unsigned long long oh2 = __shfl_xor_sync(0xFFFFFFFFu, kh[2], off);
                unsigned long long ot3 = __shfl_xor_sync(0xFFFFFFFFu, kt[3], off);
                unsigned long long oh3 = __shfl_xor_sync(0xFFFFFFFFu, kh[3], off);
                unsigned long long a0 = kt[0] > ot3 ? kt[0] : ot3;
                unsigned long long a1 = kt[1] > ot2 ? kt[1] : ot2;
                unsigned long long a2 = kt[2] > ot1 ? kt[2] : ot1;
                unsigned long long a3 = kt[3] > ot0 ? kt[3] : ot0;
                unsigned long long b0 = kh[0] > oh3 ? kh[0] : oh3;
                unsigned long long b1 = kh[1] > oh2 ? kh[1] : oh2;
                unsigned long long b2 = kh[2] > oh1 ? kh[2] : oh1;
                unsigned long long b3 = kh[3] > oh0 ? kh[3] : oh0;
                CE(a0, a2); CE(b0, b2);
                CE(a1, a3); CE(b1, b3);
                CE(a0, a1); CE(b0, b1);
                CE(a2, a3); CE(b2, b3);
                kt[0] = a0; kt[1] = a1; kt[2] = a2; kt[3] = a3;
                kh[0] = b0; kh[1] = b1; kh[2] = b2; kh[3] = b3;
            }
            if (lane == 0) {
#pragma unroll
                for (int j = 0; j < 4; j++) {
                    cand[0][warp * 4 + j] = kt[j];
                    cand[1][warp * 4 + j] = kh[j];
                }
            }
        }
        __syncthreads();

        // final merge 32 -> 4 per type (warp0 targets, warp1 holders)
        if (warp < 2) {
            const int type = warp;
            unsigned long long k0 = cand[type][lane], k1 = 0ull, k2 = 0ull, k3 = 0ull;
            WARP_MERGE4(k0, k1, k2, k3);
            if (lane == 0) {
                unsigned long long ks[4] = {k0, k1, k2, k3};
#pragma unroll
                for (int k = 0; k < KK; k++) {
                    unsigned hi = (unsigned)(ks[k] >> 32);
                    unsigned lo = (unsigned)ks[k];
                    float v = (hi & 0x80000000u) ? __uint_as_float(hi ^ 0x80000000u)
                                                 : __uint_as_float(~hi);
                    topv[type][k] = v;
                    topi[type][k] = (int)(0xFFFFFFFFu - lo);
                }
            }
        }
        __syncthreads();

        // rep dots: 1 warp per selected span (warps 0-3 target, 4-7 holder)
        {
            const int type = warp >> 2;
            const int k = warp & 3;
            const int idx = topi[type][k];
            const bool valid = topv[type][k] > 0.f;
            const int m = idx >> 7, s = idx & 127;
            const float invw = c_inv[m];
            const float4* wi4 = (const float4*)wi;
            const float4* we4 = (const float4*)we;

            float acc[8] = {0.f,0.f,0.f,0.f,0.f,0.f,0.f,0.f};
            if (valid) {
                float4 sum[6];
#pragma unroll
                for (int i = 0; i < 6; i++) sum[i] = make_float4(0.f,0.f,0.f,0.f);
#pragma unroll
                for (int r = 0; r < 8; r++) {
                    if (r <= m) {
                        const float4* rp = (const float4*)(eb + (s + r) * HZ);
#pragma unroll
                        for (int i = 0; i < 6; i++) {
                            float4 a = rp[lane + 32 * i];
                            sum[i].x += a.x; sum[i].y += a.y;
                            sum[i].z += a.z; sum[i].w += a.w;
                        }
                    }
                }
#pragma unroll
                for (int i = 0; i < 6; i++) {
                    int h4 = lane + 32 * i;
                    float sv[4] = {sum[i].x * invw, sum[i].y * invw,
                                   sum[i].z * invw, sum[i].w * invw};
#pragma unroll
                    for (int j = 0; j < 4; j++) {
                        int f = 4 * h4 + j;
                        if (type == 0) {
                            float4 wv = wi4[f];
                            acc[0] += sv[j] * wv.x; acc[1] += sv[j] * wv.y;
                            acc[2] += sv[j] * wv.z; acc[3] += sv[j] * wv.w;
                            float4 ev = we4[HZ + f];
                            acc[4] += sv[j] * ev.x; acc[5] += sv[j] * ev.y;
                            acc[6] += sv[j] * ev.z; acc[7] += sv[j] * ev.w;
                        } else {
                            float4 ev = we4[f];
                            acc[0] += sv[j] * ev.x; acc[1] += sv[j] * ev.y;
                            acc[2] += sv[j] * ev.z; acc[3] += sv[j] * ev.w;
                        }
                    }
                }
            }
#pragma unroll
            for (int off = 16; off; off >>= 1)
#pragma unroll
                for (int j = 0; j < 8; j++)
                    acc[j] += __shfl_xor_sync(0xFFFFFFFFu, acc[j], off);
            if (lane == 0) {
#pragma unroll
                for (int j = 0; j < 8; j++) partial[warp][j] = acc[j];
            }
        }
        __syncthreads();

        // logits
        if (tid < 64) {
            int k = tid >> 4, i = (tid >> 2) & 3, j = tid & 3;
            bool pv = (topv[1][k] > 0.f) && (topv[0][i] > 0.f);
            float val = sbias[4 + j];
            if (pv) val += partial[4 + k][j] + partial[i][4 + j];
            out[512 + b * 64 + tid] = val;
        } else if (tid < 80) {
            int t2 = tid - 64;
            int i = t2 >> 2, j = t2 & 3;
            float val = sbias[j];
            if (topv[0][i] > 0.f) val += partial[i][j];
            out[b * 16 + t2] = val;
        }
    }

    // all CTAs of the cluster synchronize before exit (DSMEM safety)
    CLUSTER_SYNC();
}

extern "C" void kernel_launch(void* const* d_in, const int* in_sizes, int n_in,
                              void* d_out, int out_size)
{
    const float* emb = (const float*)d_in[0];
    const int*   msk = (const int*)d_in[1];
    const float* wh  = (const float*)d_in[2];
    const float* bh  = (const float*)d_in[3];
    const float* wt  = (const float*)d_in[4];
    const float* bt  = (const float*)d_in[5];
    const float* wi  = (const float*)d_in[6];
    const float* bi  = (const float*)d_in[7];
    const float* we  = (const float*)d_in[8];
    const float* be  = (const float*)d_in[9];
    float* out = (float*)d_out;

    k_all<<<BZ * 4, 256>>>(emb, msk, wh, bh, wt, bt, wi, bi, we, be, out);
}